// round 7
// baseline (speedup 1.0000x reference)
#include <cuda_runtime.h>
#include <cuda_fp16.h>
#include <cstdint>

// PolynomialMoE: N=1048576, DIM=2, HID=64, E=4, hard top-1.
// Output (float32): [ out (N*2) | router_logits (N*4) ]
//
// R7: layer-2 GEMM as fp16 HMMA (m16n8k16) with the fp32 precision recovered
// by folding the h-residual into the K dimension:
//   A_ext[K=128] = [ fp16(h) | fp16(h - fp16(h)) ],  B_ext = [ fp16(w) | fp16(w) ]
// => (hm + hr) * wm : only w-truncation (2^-11) remains, ~1.3e-4 output err.
// B fragments are identical across the two K-halves, so each B LDS feeds 4
// MMAs (halves B traffic vs R6) and B staging is 8KB not 16KB. w1/b1
// broadcasts use contiguous float2 pairs. TILE=256 tokens per 256-thread CTA.

typedef unsigned long long U64;

static constexpr int N_MAX = 1 << 20;
static constexpr int TILE  = 256;

__device__ int d_cnt[4];
__device__ int d_perm[4 * N_MAX];
// fp16 B fragments: [e][ks(4)][nt(8)][lane(32)] uint2
__device__ uint2 d_w2f[4 * 4 * 8 * 32];

// ---------------- helpers ----------------
__device__ __forceinline__ U64 fma2(U64 a, U64 b, U64 c) {
    U64 d;
    asm("fma.rn.f32x2 %0, %1, %2, %3;" : "=l"(d) : "l"(a), "l"(b), "l"(c));
    return d;
}
__device__ __forceinline__ U64 pack2(float lo, float hi) {
    U64 r;
    asm("mov.b64 %0, {%1, %2};" : "=l"(r) : "f"(lo), "f"(hi));
    return r;
}
__device__ __forceinline__ void unpack2(U64 v, float& lo, float& hi) {
    asm("mov.b64 {%0, %1}, %2;" : "=f"(lo), "=f"(hi) : "l"(v));
}
// pack two floats to f16x2, lo = first arg
__device__ __forceinline__ uint32_t packh2(float lo, float hi) {
    uint32_t r;
    asm("cvt.rn.f16x2.f32 %0, %1, %2;" : "=r"(r) : "f"(hi), "f"(lo));
    return r;
}
__device__ __forceinline__ float2 h2f2(uint32_t p) {
    __half2 h;
    memcpy(&h, &p, 4);
    return __half22float2(h);
}
__device__ __forceinline__ void mma_f16(float c[4], const uint32_t a[4],
                                        uint32_t b0, uint32_t b1) {
    asm volatile(
        "mma.sync.aligned.m16n8k16.row.col.f32.f16.f16.f32 "
        "{%0,%1,%2,%3}, {%4,%5,%6,%7}, {%8,%9}, {%0,%1,%2,%3};"
        : "+f"(c[0]), "+f"(c[1]), "+f"(c[2]), "+f"(c[3])
        : "r"(a[0]), "r"(a[1]), "r"(a[2]), "r"(a[3]), "r"(b0), "r"(b1));
}

// ---------------- Kernel 1: router (2 tok/thread) + fused w2 prep ---------
__global__ __launch_bounds__(256)
void router_kernel(const float* __restrict__ x,
                   const float* __restrict__ rW,
                   const float* __restrict__ rb,
                   const float* __restrict__ w2,
                   float* __restrict__ out, int n)
{
    __shared__ int scnt[4], gbase[4];
    const int tid = threadIdx.x;
    if (tid < 4) scnt[tid] = 0;

    // fused prep: blocks 0-3 build expert e's fp16 B fragments (m16n8k16)
    if (blockIdx.x < 4) {
        const int e = blockIdx.x;
        #pragma unroll
        for (int t = tid; t < 1024; t += 256) {
            const int ks = t >> 8, nt = (t >> 5) & 7, lane = t & 31;
            const int k0 = ks * 16 + (lane & 3) * 2;
            const int nn = nt * 8 + (lane >> 2);
            const float v00 = w2[e * 4096 + k0 * 64 + nn];
            const float v01 = w2[e * 4096 + (k0 + 1) * 64 + nn];
            const float v10 = w2[e * 4096 + (k0 + 8) * 64 + nn];
            const float v11 = w2[e * 4096 + (k0 + 9) * 64 + nn];
            d_w2f[((e * 4 + ks) * 8 + nt) * 32 + lane] =
                make_uint2(packh2(v00, v01), packh2(v10, v11));
        }
    }
    __syncthreads();

    const float rw0 = rW[0], rw1 = rW[1], rw2 = rW[2], rw3 = rW[3];
    const float rw4 = rW[4], rw5 = rW[5], rw6 = rW[6], rw7 = rW[7];
    const float rb0 = rb[0], rb1 = rb[1], rb2 = rb[2], rb3 = rb[3];

    const int base = blockIdx.x * 512;                // 2 tokens per thread
    const float4 xq = ((const float4*)x)[base / 2 + tid];
    const unsigned lane = tid & 31;

    int bests[2], wbs[2];
    #pragma unroll
    for (int s = 0; s < 2; s++) {
        const int i = base + 2 * tid + s;
        const float x0 = s ? xq.z : xq.x;
        const float x1 = s ? xq.w : xq.y;
        const float l0 = fmaf(x0, rw0, fmaf(x1, rw4, rb0));
        const float l1 = fmaf(x0, rw1, fmaf(x1, rw5, rb1));
        const float l2 = fmaf(x0, rw2, fmaf(x1, rw6, rb2));
        const float l3 = fmaf(x0, rw3, fmaf(x1, rw7, rb3));
        int best = 0; float bl = l0;
        if (l1 > bl) { bl = l1; best = 1; }
        if (l2 > bl) { bl = l2; best = 2; }
        if (l3 > bl) { bl = l3; best = 3; }
        ((float4*)(out + 2 * (size_t)n))[i] = make_float4(l0, l1, l2, l3);

        unsigned m[4];
        #pragma unroll
        for (int e = 0; e < 4; e++)
            m[e] = __ballot_sync(0xffffffffu, best == e);
        const unsigned mym = m[best];
        const int rank   = __popc(mym & ((1u << lane) - 1));
        const int leader = __ffs(mym) - 1;
        int wb = 0;
        if ((int)lane == leader) wb = atomicAdd(&scnt[best], __popc(mym));
        wb = __shfl_sync(0xffffffffu, wb, leader);
        bests[s] = best;
        wbs[s] = wb + rank;
    }
    __syncthreads();
    if (tid < 4) gbase[tid] = atomicAdd(&d_cnt[tid], scnt[tid]);
    __syncthreads();

    #pragma unroll
    for (int s = 0; s < 2; s++)
        d_perm[bests[s] * N_MAX + gbase[bests[s]] + wbs[s]] = base + 2 * tid + s;
}

// ---------------- Kernel 2: expert tile (fp16 HMMA, residual-in-K) --------
__global__ __launch_bounds__(256, 2)
void expert_kernel(const float* __restrict__ x,
                   const float* __restrict__ w1,
                   const float* __restrict__ b1,
                   const float* __restrict__ b2,
                   const float* __restrict__ w3,
                   const float* __restrict__ b3,
                   float* __restrict__ out)
{
    __shared__ uint2  sBf[1024];          // [ks(4)][nt(8)][lane(32)]
    __shared__ float2 sX[256];
    __shared__ float  sW1[128];           // [d][i]
    __shared__ float  sB1[64], sB2[64];
    __shared__ __align__(8) float sW3[128];
    __shared__ float  sB3[2];
    __shared__ int    sIdx[256];

    // --- map blockIdx -> (expert, tile) ---
    const int c0 = d_cnt[0], c1 = d_cnt[1], c2 = d_cnt[2], c3 = d_cnt[3];
    const int t0 = (c0 + TILE - 1) / TILE, t1 = (c1 + TILE - 1) / TILE;
    const int t2 = (c2 + TILE - 1) / TILE, t3 = (c3 + TILE - 1) / TILE;
    int b = blockIdx.x, e, lo, cnt;
    if (b < t0)              { e = 0; lo = b; cnt = c0; }
    else if ((b -= t0) < t1) { e = 1; lo = b; cnt = c1; }
    else if ((b -= t1) < t2) { e = 2; lo = b; cnt = c2; }
    else if ((b -= t2) < t3) { e = 3; lo = b; cnt = c3; }
    else return;

    const int tid = threadIdx.x;
    const int tstart = lo * TILE;
    int mvalid = cnt - tstart;
    if (mvalid > TILE) mvalid = TILE;

    // --- stage ---
    {
        const uint4* gB = ((const uint4*)d_w2f) + e * 512;
        uint4* sB4 = (uint4*)sBf;
        #pragma unroll
        for (int t = tid; t < 512; t += 256) sB4[t] = gB[t];
        if (tid < 128) { sW1[tid] = w1[e * 128 + tid]; sW3[tid] = w3[e * 128 + tid]; }
        else if (tid < 192) {
            const int i = tid - 128;
            sB1[i] = b1[e * 64 + i];
            sB2[i] = b2[e * 64 + i];
        }
        if (tid < 2) sB3[tid] = b3[e * 2 + tid];
        const int token = d_perm[e * N_MAX + tstart + (tid < mvalid ? tid : 0)];
        sIdx[tid] = token;
        sX[tid] = ((const float2*)x)[token];
    }
    __syncthreads();

    const int lane = tid & 31, wid = tid >> 5;
    const int qr = lane >> 2;             // row-in-8
    const int kb = lane & 3;
    const int rbase = wid * 32 + qr;

    float xr[4], yr[4];                   // rows rbase + {0,8,16,24}
    #pragma unroll
    for (int r = 0; r < 4; r++) {
        const float2 v = sX[rbase + r * 8];
        xr[r] = v.x; yr[r] = v.y;
    }

    float acc[2][8][4];
    #pragma unroll
    for (int mt = 0; mt < 2; mt++)
        #pragma unroll
        for (int nt = 0; nt < 8; nt++)
            #pragma unroll
            for (int q = 0; q < 4; q++) acc[mt][nt][q] = 0.f;

    #pragma unroll
    for (int ks = 0; ks < 4; ks++) {
        const int k = ks * 16 + kb * 2;   // this thread's k pair base (even)
        const float2 wa0 = *(const float2*)&sW1[k];
        const float2 wa8 = *(const float2*)&sW1[k + 8];
        const float2 wb0 = *(const float2*)&sW1[64 + k];
        const float2 wb8 = *(const float2*)&sW1[64 + k + 8];
        const float2 bb0 = *(const float2*)&sB1[k];
        const float2 bb8 = *(const float2*)&sB1[k + 8];

        uint32_t Am[2][4], Ar[2][4];
        #pragma unroll
        for (int r = 0; r < 4; r++) {     // r = 2*mt + p (p: row +0 / +8)
            const float h0 = fmaxf(fmaf(xr[r], wa0.x, fmaf(yr[r], wb0.x, bb0.x)), 0.f);
            const float h1 = fmaxf(fmaf(xr[r], wa0.y, fmaf(yr[r], wb0.y, bb0.y)), 0.f);
            const float h8 = fmaxf(fmaf(xr[r], wa8.x, fmaf(yr[r], wb8.x, bb8.x)), 0.f);
            const float h9 = fmaxf(fmaf(xr[r], wa8.y, fmaf(yr[r], wb8.y, bb8.y)), 0.f);
            const uint32_t m01 = packh2(h0, h1);
            const uint32_t m89 = packh2(h8, h9);
            const float2 f01 = h2f2(m01);
            const float2 f89 = h2f2(m89);
            const uint32_t r01 = packh2(h0 - f01.x, h1 - f01.y);
            const uint32_t r89 = packh2(h8 - f89.x, h9 - f89.y);
            const int mt = r >> 1, p = r & 1;
            Am[mt][p]     = m01;  Am[mt][p + 2] = m89;
            Ar[mt][p]     = r01;  Ar[mt][p + 2] = r89;
        }

        #pragma unroll
        for (int nt = 0; nt < 8; nt++) {
            const uint2 B = sBf[(ks * 8 + nt) * 32 + lane];
            mma_f16(acc[0][nt], Am[0], B.x, B.y);
            mma_f16(acc[1][nt], Am[1], B.x, B.y);
            mma_f16(acc[0][nt], Ar[0], B.x, B.y);
            mma_f16(acc[1][nt], Ar[1], B.x, B.y);
        }
    }

    // --- epilogue: b2 + relu + fused layer 3, reduce over 4 n-lanes ---
    const U64* w3p = (const U64*)sW3;
    const int jb = kb * 2;
    #pragma unroll
    for (int mt = 0; mt < 2; mt++) {
        U64 po0 = 0ull, po1 = 0ull;
        #pragma unroll
        for (int nt = 0; nt < 8; nt++) {
            const int j0 = nt * 8 + jb, j1 = j0 + 1;
            float c;
            c = fmaxf(acc[mt][nt][0] + sB2[j0], 0.f);
            po0 = fma2(pack2(c, c), w3p[j0], po0);
            c = fmaxf(acc[mt][nt][1] + sB2[j1], 0.f);
            po0 = fma2(pack2(c, c), w3p[j1], po0);
            c = fmaxf(acc[mt][nt][2] + sB2[j0], 0.f);
            po1 = fma2(pack2(c, c), w3p[j0], po1);
            c = fmaxf(acc[mt][nt][3] + sB2[j1], 0.f);
            po1 = fma2(pack2(c, c), w3p[j1], po1);
        }
        float a0, a1, c0v, c1v;
        unpack2(po0, a0, a1);
        unpack2(po1, c0v, c1v);
        #pragma unroll
        for (int s = 1; s < 4; s <<= 1) {
            a0  += __shfl_xor_sync(0xffffffffu, a0,  s);
            a1  += __shfl_xor_sync(0xffffffffu, a1,  s);
            c0v += __shfl_xor_sync(0xffffffffu, c0v, s);
            c1v += __shfl_xor_sync(0xffffffffu, c1v, s);
        }
        if (kb == 0) {
            const int r0 = wid * 32 + mt * 16 + qr;
            if (r0 < mvalid)
                ((float2*)out)[sIdx[r0]] = make_float2(a0 + sB3[0], a1 + sB3[1]);
            const int r1 = r0 + 8;
            if (r1 < mvalid)
                ((float2*)out)[sIdx[r1]] = make_float2(c0v + sB3[0], c1v + sB3[1]);
        }
    }
}

extern "C" void kernel_launch(void* const* d_in, const int* in_sizes, int n_in,
                              void* d_out, int out_size)
{
    const float* x  = (const float*)d_in[0];
    const float* rW = (const float*)d_in[1];
    const float* rb = (const float*)d_in[2];
    const float* w1 = (const float*)d_in[3];
    const float* b1 = (const float*)d_in[4];
    const float* w2 = (const float*)d_in[5];
    const float* b2 = (const float*)d_in[6];
    const float* w3 = (const float*)d_in[7];
    const float* b3 = (const float*)d_in[8];
    float* out = (float*)d_out;

    const int n_tok = in_sizes[0] / 2;

    void* cnt_addr = nullptr;
    cudaGetSymbolAddress(&cnt_addr, d_cnt);
    cudaMemsetAsync(cnt_addr, 0, 4 * sizeof(int));

    router_kernel<<<n_tok / 512, 256>>>(x, rW, rb, w2, out, n_tok);

    const int max_tiles = n_tok / TILE + 3;   // per-expert ceil slack
    expert_kernel<<<max_tiles, 256>>>(x, w1, b1, b2, w3, b3, out);
}

// round 8
// speedup vs baseline: 1.1973x; 1.1973x over previous
#include <cuda_runtime.h>
#include <cuda_fp16.h>
#include <cstdint>

// PolynomialMoE: N=1048576, DIM=2, HID=64, E=4, hard top-1.
// Output (float32): [ out (N*2) | router_logits (N*4) ]
//
// R8: pure fp16 single-product HMMA (m16n8k16). R7 showed the expert kernel
// is ISSUE-bound (no pipe >46%), so this halves the instruction stream:
// 64 MMAs/warp (was 128), no residual split in the A-build, b2 folded into
// the accumulator init. Precision anchor: R6 tf32 (same 11-bit mantissa on
// both operands) measured 1.86e-4 -> pure fp16 expected ~2e-4 << 1e-3.

typedef unsigned long long U64;

static constexpr int N_MAX = 1 << 20;
static constexpr int TILE  = 256;

__device__ int d_cnt[4];
__device__ int d_perm[4 * N_MAX];
// fp16 B fragments: [e][ks(4)][nt(8)][lane(32)] uint2
__device__ uint2 d_w2f[4 * 4 * 8 * 32];

// ---------------- helpers ----------------
__device__ __forceinline__ U64 fma2(U64 a, U64 b, U64 c) {
    U64 d;
    asm("fma.rn.f32x2 %0, %1, %2, %3;" : "=l"(d) : "l"(a), "l"(b), "l"(c));
    return d;
}
__device__ __forceinline__ U64 pack2(float lo, float hi) {
    U64 r;
    asm("mov.b64 %0, {%1, %2};" : "=l"(r) : "f"(lo), "f"(hi));
    return r;
}
__device__ __forceinline__ void unpack2(U64 v, float& lo, float& hi) {
    asm("mov.b64 {%0, %1}, %2;" : "=f"(lo), "=f"(hi) : "l"(v));
}
// pack two floats to f16x2, lo = first arg
__device__ __forceinline__ uint32_t packh2(float lo, float hi) {
    uint32_t r;
    asm("cvt.rn.f16x2.f32 %0, %1, %2;" : "=r"(r) : "f"(hi), "f"(lo));
    return r;
}
__device__ __forceinline__ void mma_f16(float c[4], const uint32_t a[4],
                                        uint32_t b0, uint32_t b1) {
    asm volatile(
        "mma.sync.aligned.m16n8k16.row.col.f32.f16.f16.f32 "
        "{%0,%1,%2,%3}, {%4,%5,%6,%7}, {%8,%9}, {%0,%1,%2,%3};"
        : "+f"(c[0]), "+f"(c[1]), "+f"(c[2]), "+f"(c[3])
        : "r"(a[0]), "r"(a[1]), "r"(a[2]), "r"(a[3]), "r"(b0), "r"(b1));
}

// ---------------- Kernel 1: router (2 tok/thread) + fused w2 prep ---------
__global__ __launch_bounds__(256)
void router_kernel(const float* __restrict__ x,
                   const float* __restrict__ rW,
                   const float* __restrict__ rb,
                   const float* __restrict__ w2,
                   float* __restrict__ out, int n)
{
    __shared__ int scnt[4], gbase[4];
    const int tid = threadIdx.x;
    if (tid < 4) scnt[tid] = 0;

    // fused prep: blocks 0-3 build expert e's fp16 B fragments (m16n8k16)
    if (blockIdx.x < 4) {
        const int e = blockIdx.x;
        #pragma unroll
        for (int t = tid; t < 1024; t += 256) {
            const int ks = t >> 8, nt = (t >> 5) & 7, lane = t & 31;
            const int k0 = ks * 16 + (lane & 3) * 2;
            const int nn = nt * 8 + (lane >> 2);
            const float v00 = w2[e * 4096 + k0 * 64 + nn];
            const float v01 = w2[e * 4096 + (k0 + 1) * 64 + nn];
            const float v10 = w2[e * 4096 + (k0 + 8) * 64 + nn];
            const float v11 = w2[e * 4096 + (k0 + 9) * 64 + nn];
            d_w2f[((e * 4 + ks) * 8 + nt) * 32 + lane] =
                make_uint2(packh2(v00, v01), packh2(v10, v11));
        }
    }
    __syncthreads();

    const float rw0 = rW[0], rw1 = rW[1], rw2 = rW[2], rw3 = rW[3];
    const float rw4 = rW[4], rw5 = rW[5], rw6 = rW[6], rw7 = rW[7];
    const float rb0 = rb[0], rb1 = rb[1], rb2 = rb[2], rb3 = rb[3];

    const int base = blockIdx.x * 512;                // 2 tokens per thread
    const float4 xq = ((const float4*)x)[base / 2 + tid];
    const unsigned lane = tid & 31;

    int bests[2], wbs[2];
    #pragma unroll
    for (int s = 0; s < 2; s++) {
        const int i = base + 2 * tid + s;
        const float x0 = s ? xq.z : xq.x;
        const float x1 = s ? xq.w : xq.y;
        const float l0 = fmaf(x0, rw0, fmaf(x1, rw4, rb0));
        const float l1 = fmaf(x0, rw1, fmaf(x1, rw5, rb1));
        const float l2 = fmaf(x0, rw2, fmaf(x1, rw6, rb2));
        const float l3 = fmaf(x0, rw3, fmaf(x1, rw7, rb3));
        int best = 0; float bl = l0;
        if (l1 > bl) { bl = l1; best = 1; }
        if (l2 > bl) { bl = l2; best = 2; }
        if (l3 > bl) { bl = l3; best = 3; }
        ((float4*)(out + 2 * (size_t)n))[i] = make_float4(l0, l1, l2, l3);

        unsigned m[4];
        #pragma unroll
        for (int e = 0; e < 4; e++)
            m[e] = __ballot_sync(0xffffffffu, best == e);
        const unsigned mym = m[best];
        const int rank   = __popc(mym & ((1u << lane) - 1));
        const int leader = __ffs(mym) - 1;
        int wb = 0;
        if ((int)lane == leader) wb = atomicAdd(&scnt[best], __popc(mym));
        wb = __shfl_sync(0xffffffffu, wb, leader);
        bests[s] = best;
        wbs[s] = wb + rank;
    }
    __syncthreads();
    if (tid < 4) gbase[tid] = atomicAdd(&d_cnt[tid], scnt[tid]);
    __syncthreads();

    #pragma unroll
    for (int s = 0; s < 2; s++)
        d_perm[bests[s] * N_MAX + gbase[bests[s]] + wbs[s]] = base + 2 * tid + s;
}

// ---------------- Kernel 2: expert tile (pure fp16 HMMA) ------------------
__global__ __launch_bounds__(256, 2)
void expert_kernel(const float* __restrict__ x,
                   const float* __restrict__ w1,
                   const float* __restrict__ b1,
                   const float* __restrict__ b2,
                   const float* __restrict__ w3,
                   const float* __restrict__ b3,
                   float* __restrict__ out)
{
    __shared__ uint2  sBf[1024];          // [ks(4)][nt(8)][lane(32)]
    __shared__ float2 sX[256];
    __shared__ float  sW1[128];           // [d][i]
    __shared__ float  sB1[64], sB2[64];
    __shared__ __align__(8) float sW3[128];
    __shared__ float  sB3[2];
    __shared__ int    sIdx[256];

    // --- map blockIdx -> (expert, tile) ---
    const int c0 = d_cnt[0], c1 = d_cnt[1], c2 = d_cnt[2], c3 = d_cnt[3];
    const int t0 = (c0 + TILE - 1) / TILE, t1 = (c1 + TILE - 1) / TILE;
    const int t2 = (c2 + TILE - 1) / TILE, t3 = (c3 + TILE - 1) / TILE;
    int b = blockIdx.x, e, lo, cnt;
    if (b < t0)              { e = 0; lo = b; cnt = c0; }
    else if ((b -= t0) < t1) { e = 1; lo = b; cnt = c1; }
    else if ((b -= t1) < t2) { e = 2; lo = b; cnt = c2; }
    else if ((b -= t2) < t3) { e = 3; lo = b; cnt = c3; }
    else return;

    const int tid = threadIdx.x;
    const int tstart = lo * TILE;
    int mvalid = cnt - tstart;
    if (mvalid > TILE) mvalid = TILE;

    // --- stage ---
    {
        const uint4* gB = ((const uint4*)d_w2f) + e * 512;
        uint4* sB4 = (uint4*)sBf;
        #pragma unroll
        for (int t = tid; t < 512; t += 256) sB4[t] = gB[t];
        if (tid < 128) { sW1[tid] = w1[e * 128 + tid]; sW3[tid] = w3[e * 128 + tid]; }
        else if (tid < 192) {
            const int i = tid - 128;
            sB1[i] = b1[e * 64 + i];
            sB2[i] = b2[e * 64 + i];
        }
        if (tid < 2) sB3[tid] = b3[e * 2 + tid];
        const int token = d_perm[e * N_MAX + tstart + (tid < mvalid ? tid : 0)];
        sIdx[tid] = token;
        sX[tid] = ((const float2*)x)[token];
    }
    __syncthreads();

    const int lane = tid & 31, wid = tid >> 5;
    const int qr = lane >> 2;             // row-in-8
    const int kb = lane & 3;
    const int rbase = wid * 32 + qr;
    const int jb = kb * 2;

    float xr[4], yr[4];                   // rows rbase + {0,8,16,24}
    #pragma unroll
    for (int r = 0; r < 4; r++) {
        const float2 v = sX[rbase + r * 8];
        xr[r] = v.x; yr[r] = v.y;
    }

    // acc init = b2 (folded layer-2 bias): element q of acc[mt][nt] is
    // column j = nt*8 + jb + (q&1); rows differ across q>>1 only.
    float acc[2][8][4];
    #pragma unroll
    for (int nt = 0; nt < 8; nt++) {
        const float bj0 = sB2[nt * 8 + jb], bj1 = sB2[nt * 8 + jb + 1];
        #pragma unroll
        for (int mt = 0; mt < 2; mt++) {
            acc[mt][nt][0] = bj0; acc[mt][nt][1] = bj1;
            acc[mt][nt][2] = bj0; acc[mt][nt][3] = bj1;
        }
    }

    #pragma unroll
    for (int ks = 0; ks < 4; ks++) {
        const int k = ks * 16 + kb * 2;   // this thread's k pair base (even)
        const float2 wa0 = *(const float2*)&sW1[k];
        const float2 wa8 = *(const float2*)&sW1[k + 8];
        const float2 wb0 = *(const float2*)&sW1[64 + k];
        const float2 wb8 = *(const float2*)&sW1[64 + k + 8];
        const float2 bb0 = *(const float2*)&sB1[k];
        const float2 bb8 = *(const float2*)&sB1[k + 8];

        uint32_t A[2][4];
        #pragma unroll
        for (int r = 0; r < 4; r++) {     // r = 2*mt + p (p: row +0 / +8)
            const float h0 = fmaxf(fmaf(xr[r], wa0.x, fmaf(yr[r], wb0.x, bb0.x)), 0.f);
            const float h1 = fmaxf(fmaf(xr[r], wa0.y, fmaf(yr[r], wb0.y, bb0.y)), 0.f);
            const float h8 = fmaxf(fmaf(xr[r], wa8.x, fmaf(yr[r], wb8.x, bb8.x)), 0.f);
            const float h9 = fmaxf(fmaf(xr[r], wa8.y, fmaf(yr[r], wb8.y, bb8.y)), 0.f);
            const int mt = r >> 1, p = r & 1;
            A[mt][p]     = packh2(h0, h1);
            A[mt][p + 2] = packh2(h8, h9);
        }

        #pragma unroll
        for (int nt = 0; nt < 8; nt++) {
            const uint2 B = sBf[(ks * 8 + nt) * 32 + lane];
            mma_f16(acc[0][nt], A[0], B.x, B.y);
            mma_f16(acc[1][nt], A[1], B.x, B.y);
        }
    }

    // --- epilogue: relu + fused layer 3, reduce over 4 n-lanes ---
    const U64* w3p = (const U64*)sW3;
    #pragma unroll
    for (int mt = 0; mt < 2; mt++) {
        U64 po0 = 0ull, po1 = 0ull;
        #pragma unroll
        for (int nt = 0; nt < 8; nt++) {
            const int j0 = nt * 8 + jb, j1 = j0 + 1;
            float c;
            c = fmaxf(acc[mt][nt][0], 0.f);
            po0 = fma2(pack2(c, c), w3p[j0], po0);
            c = fmaxf(acc[mt][nt][1], 0.f);
            po0 = fma2(pack2(c, c), w3p[j1], po0);
            c = fmaxf(acc[mt][nt][2], 0.f);
            po1 = fma2(pack2(c, c), w3p[j0], po1);
            c = fmaxf(acc[mt][nt][3], 0.f);
            po1 = fma2(pack2(c, c), w3p[j1], po1);
        }
        float a0, a1, c0v, c1v;
        unpack2(po0, a0, a1);
        unpack2(po1, c0v, c1v);
        #pragma unroll
        for (int s = 1; s < 4; s <<= 1) {
            a0  += __shfl_xor_sync(0xffffffffu, a0,  s);
            a1  += __shfl_xor_sync(0xffffffffu, a1,  s);
            c0v += __shfl_xor_sync(0xffffffffu, c0v, s);
            c1v += __shfl_xor_sync(0xffffffffu, c1v, s);
        }
        if (kb == 0) {
            const int r0 = wid * 32 + mt * 16 + qr;
            if (r0 < mvalid)
                ((float2*)out)[sIdx[r0]] = make_float2(a0 + sB3[0], a1 + sB3[1]);
            const int r1 = r0 + 8;
            if (r1 < mvalid)
                ((float2*)out)[sIdx[r1]] = make_float2(c0v + sB3[0], c1v + sB3[1]);
        }
    }
}

extern "C" void kernel_launch(void* const* d_in, const int* in_sizes, int n_in,
                              void* d_out, int out_size)
{
    const float* x  = (const float*)d_in[0];
    const float* rW = (const float*)d_in[1];
    const float* rb = (const float*)d_in[2];
    const float* w1 = (const float*)d_in[3];
    const float* b1 = (const float*)d_in[4];
    const float* w2 = (const float*)d_in[5];
    const float* b2 = (const float*)d_in[6];
    const float* w3 = (const float*)d_in[7];
    const float* b3 = (const float*)d_in[8];
    float* out = (float*)d_out;

    const int n_tok = in_sizes[0] / 2;

    void* cnt_addr = nullptr;
    cudaGetSymbolAddress(&cnt_addr, d_cnt);
    cudaMemsetAsync(cnt_addr, 0, 4 * sizeof(int));

    router_kernel<<<n_tok / 512, 256>>>(x, rW, rb, w2, out, n_tok);

    const int max_tiles = n_tok / TILE + 3;   // per-expert ceil slack
    expert_kernel<<<max_tiles, 256>>>(x, w1, b1, b2, w3, b3, out);
}

// round 9
// speedup vs baseline: 1.3849x; 1.1567x over previous
#include <cuda_runtime.h>
#include <cuda_fp16.h>
#include <cstdint>

// PolynomialMoE: N=1048576, DIM=2, HID=64, E=4, hard top-1.
// Output (float32): [ out (N*2) | router_logits (N*4) ]
//
// R9: ALL three layers on the HMMA pipe (issue-bound kernel -> cut the
// instruction stream). Fragment identity: the m16n8k16 D-fragment layout of
// layer L equals the A-fragment layout of layer L+1 when N-tiles are paired
// (nt=2ks,2ks+1 -> k in [16ks,16ks+16)). So:
//   L1: X_ext=[x0,x1,1,0..] (fp16) @ W1_ext=[w1;b1;0]  (4 MMAs/ks)
//   L2: relu-repacked L1 D-frags @ w2 frags            (16 MMAs/ks)
//   L3: relu-repacked L2 accs @ w3 padded to N=8       (8 MMAs, replaces
//       the 64 fma2 + 24 shfl epilogue; kb==0 lanes hold cols 0,1)
// b1 folded via X col2=1; b2 folded into L2 acc init; fp32 accum throughout.

typedef unsigned long long U64;

static constexpr int N_MAX = 1 << 20;
static constexpr int TILE  = 256;

__device__ int d_cnt[4];
__device__ int d_perm[4 * N_MAX];
__device__ uint2 d_w2f[4 * 1024];   // [e][ks(4)][nt(8)][lane(32)]
__device__ uint2 d_w1f[4 * 256];    // [e][nt(8)][lane(32)]
__device__ uint2 d_w3f[4 * 128];    // [e][ks(4)][lane(32)]

// ---------------- helpers ----------------
// pack two floats to f16x2, lo = first arg
__device__ __forceinline__ uint32_t packh2(float lo, float hi) {
    uint32_t r;
    asm("cvt.rn.f16x2.f32 %0, %1, %2;" : "=r"(r) : "f"(hi), "f"(lo));
    return r;
}
__device__ __forceinline__ void mma_f16(float c[4], uint32_t a0, uint32_t a1,
                                        uint32_t a2, uint32_t a3,
                                        uint32_t b0, uint32_t b1) {
    asm volatile(
        "mma.sync.aligned.m16n8k16.row.col.f32.f16.f16.f32 "
        "{%0,%1,%2,%3}, {%4,%5,%6,%7}, {%8,%9}, {%0,%1,%2,%3};"
        : "+f"(c[0]), "+f"(c[1]), "+f"(c[2]), "+f"(c[3])
        : "r"(a0), "r"(a1), "r"(a2), "r"(a3), "r"(b0), "r"(b1));
}

// ---------------- Kernel 1: router (2 tok/thread) + fused weight prep ----
__global__ __launch_bounds__(256)
void router_kernel(const float* __restrict__ x,
                   const float* __restrict__ rW,
                   const float* __restrict__ rb,
                   const float* __restrict__ w1,
                   const float* __restrict__ b1,
                   const float* __restrict__ w2,
                   const float* __restrict__ w3,
                   float* __restrict__ out, int n)
{
    __shared__ int scnt[4], gbase[4];
    const int tid = threadIdx.x;
    if (tid < 4) scnt[tid] = 0;

    if (blockIdx.x < 4) {
        // blocks 0-3: w2 fragments for expert e
        const int e = blockIdx.x;
        #pragma unroll
        for (int t = tid; t < 1024; t += 256) {
            const int ks = t >> 8, nt = (t >> 5) & 7, lane = t & 31;
            const int k0 = ks * 16 + (lane & 3) * 2;
            const int nn = nt * 8 + (lane >> 2);
            d_w2f[e * 1024 + t] = make_uint2(
                packh2(w2[e * 4096 + k0 * 64 + nn],
                       w2[e * 4096 + (k0 + 1) * 64 + nn]),
                packh2(w2[e * 4096 + (k0 + 8) * 64 + nn],
                       w2[e * 4096 + (k0 + 9) * 64 + nn]));
        }
    } else if (blockIdx.x < 8) {
        // blocks 4-7: w1_ext and w3 fragments for expert e
        const int e = blockIdx.x - 4;
        {   // w1f: [nt][lane]; K rows: 0=w1[d0], 1=w1[d1], 2=b1, 3..15=0
            const int t = tid;           // 256 threads exactly
            const int lane = t & 31, kb = lane & 3;
            const int nn = ((t >> 5) & 7) * 8 + (lane >> 2);
            uint32_t b0 = 0;
            if (kb == 0) b0 = packh2(w1[e * 128 + nn], w1[e * 128 + 64 + nn]);
            else if (kb == 1) b0 = packh2(b1[e * 64 + nn], 0.f);
            d_w1f[e * 256 + t] = make_uint2(b0, 0u);
        }
        if (tid < 128) {  // w3f: [ks][lane]; N=8 padded, cols 0,1 = w3
            const int t = tid;
            const int ks = t >> 5, lane = t & 31;
            const int col = lane >> 2;
            const int k0 = ks * 16 + (lane & 3) * 2;
            uint2 v = make_uint2(0u, 0u);
            if (col < 2) {
                v.x = packh2(w3[e * 128 + k0 * 2 + col],
                             w3[e * 128 + (k0 + 1) * 2 + col]);
                v.y = packh2(w3[e * 128 + (k0 + 8) * 2 + col],
                             w3[e * 128 + (k0 + 9) * 2 + col]);
            }
            d_w3f[e * 128 + t] = v;
        }
    }
    __syncthreads();

    const float rw0 = rW[0], rw1 = rW[1], rw2 = rW[2], rw3 = rW[3];
    const float rw4 = rW[4], rw5 = rW[5], rw6 = rW[6], rw7 = rW[7];
    const float rb0 = rb[0], rb1 = rb[1], rb2 = rb[2], rb3 = rb[3];

    const int base = blockIdx.x * 512;
    const float4 xq = ((const float4*)x)[base / 2 + tid];
    const unsigned lane = tid & 31;

    int bests[2], wbs[2];
    #pragma unroll
    for (int s = 0; s < 2; s++) {
        const int i = base + 2 * tid + s;
        const float x0 = s ? xq.z : xq.x;
        const float x1 = s ? xq.w : xq.y;
        const float l0 = fmaf(x0, rw0, fmaf(x1, rw4, rb0));
        const float l1 = fmaf(x0, rw1, fmaf(x1, rw5, rb1));
        const float l2 = fmaf(x0, rw2, fmaf(x1, rw6, rb2));
        const float l3 = fmaf(x0, rw3, fmaf(x1, rw7, rb3));
        int best = 0; float bl = l0;
        if (l1 > bl) { bl = l1; best = 1; }
        if (l2 > bl) { bl = l2; best = 2; }
        if (l3 > bl) { bl = l3; best = 3; }
        ((float4*)(out + 2 * (size_t)n))[i] = make_float4(l0, l1, l2, l3);

        unsigned m[4];
        #pragma unroll
        for (int e = 0; e < 4; e++)
            m[e] = __ballot_sync(0xffffffffu, best == e);
        const unsigned mym = m[best];
        const int rank   = __popc(mym & ((1u << lane) - 1));
        const int leader = __ffs(mym) - 1;
        int wb = 0;
        if ((int)lane == leader) wb = atomicAdd(&scnt[best], __popc(mym));
        wb = __shfl_sync(0xffffffffu, wb, leader);
        bests[s] = best;
        wbs[s] = wb + rank;
    }
    __syncthreads();
    if (tid < 4) gbase[tid] = atomicAdd(&d_cnt[tid], scnt[tid]);
    __syncthreads();

    #pragma unroll
    for (int s = 0; s < 2; s++)
        d_perm[bests[s] * N_MAX + gbase[bests[s]] + wbs[s]] = base + 2 * tid + s;
}

// ---------------- Kernel 2: expert tile (all-MMA pipeline) ----------------
__global__ __launch_bounds__(256, 2)
void expert_kernel(const float* __restrict__ x,
                   const float* __restrict__ b2,
                   const float* __restrict__ b3,
                   float* __restrict__ out)
{
    __shared__ uint2  sW2f[1024];
    __shared__ uint2  sW1f[256];
    __shared__ uint2  sW3f[128];
    __shared__ float2 sX[256];
    __shared__ float  sB2[64];
    __shared__ float  sB3[2];
    __shared__ int    sIdx[256];

    // --- map blockIdx -> (expert, tile) ---
    const int c0 = d_cnt[0], c1 = d_cnt[1], c2 = d_cnt[2], c3 = d_cnt[3];
    const int t0 = (c0 + TILE - 1) / TILE, t1 = (c1 + TILE - 1) / TILE;
    const int t2 = (c2 + TILE - 1) / TILE, t3 = (c3 + TILE - 1) / TILE;
    int b = blockIdx.x, e, lo, cnt;
    if (b < t0)              { e = 0; lo = b; cnt = c0; }
    else if ((b -= t0) < t1) { e = 1; lo = b; cnt = c1; }
    else if ((b -= t1) < t2) { e = 2; lo = b; cnt = c2; }
    else if ((b -= t2) < t3) { e = 3; lo = b; cnt = c3; }
    else return;

    const int tid = threadIdx.x;
    const int tstart = lo * TILE;
    int mvalid = cnt - tstart;
    if (mvalid > TILE) mvalid = TILE;

    // --- stage ---
    {
        const uint4* g2 = (const uint4*)(d_w2f + e * 1024);
        #pragma unroll
        for (int t = tid; t < 512; t += 256) ((uint4*)sW2f)[t] = g2[t];
        const uint4* g1 = (const uint4*)(d_w1f + e * 256);
        if (tid < 128) ((uint4*)sW1f)[tid] = g1[tid];
        else if (tid < 192) ((uint4*)sW3f)[tid - 128] = ((const uint4*)(d_w3f + e * 128))[tid - 128];
        else if (tid < 256) {
            const int i = tid - 192;
            sB2[i] = b2[e * 64 + i];
        }
        if (tid < 2) sB3[tid] = b3[e * 2 + tid];
        const int token = d_perm[e * N_MAX + tstart + (tid < mvalid ? tid : 0)];
        sIdx[tid] = token;
        sX[tid] = ((const float2*)x)[token];
    }
    __syncthreads();

    const int lane = tid & 31, wid = tid >> 5;
    const int qr = lane >> 2;
    const int kb = lane & 3;
    const int rbase = wid * 32 + qr;
    const int jb = kb * 2;

    // --- X_ext A-fragments: cols 0,1 = x0,x1 (kb==0); col 2 = 1 (kb==1) ---
    uint32_t xa[2][2];                    // [mt][row p]; a2,a3 = 0
    #pragma unroll
    for (int mt = 0; mt < 2; mt++) {
        const float2 v0 = sX[rbase + mt * 16];
        const float2 v1 = sX[rbase + mt * 16 + 8];
        uint32_t p0 = 0u, p1 = 0u;
        if (kb == 0)      { p0 = packh2(v0.x, v0.y); p1 = packh2(v1.x, v1.y); }
        else if (kb == 1) { p0 = 0x00003C00u;        p1 = 0x00003C00u; }
        xa[mt][0] = p0; xa[mt][1] = p1;
    }

    // --- L2 acc init = b2 ---
    float acc[2][8][4];
    #pragma unroll
    for (int nt = 0; nt < 8; nt++) {
        const float bj0 = sB2[nt * 8 + jb], bj1 = sB2[nt * 8 + jb + 1];
        #pragma unroll
        for (int mt = 0; mt < 2; mt++) {
            acc[mt][nt][0] = bj0; acc[mt][nt][1] = bj1;
            acc[mt][nt][2] = bj0; acc[mt][nt][3] = bj1;
        }
    }

    #pragma unroll
    for (int ks = 0; ks < 4; ks++) {
        // L1: produce h for cols [16ks, 16ks+16) = N-tiles 2ks, 2ks+1
        float l1[2][2][4];
        #pragma unroll
        for (int mt = 0; mt < 2; mt++)
            #pragma unroll
            for (int ntl = 0; ntl < 2; ntl++)
                #pragma unroll
                for (int q = 0; q < 4; q++) l1[mt][ntl][q] = 0.f;
        #pragma unroll
        for (int ntl = 0; ntl < 2; ntl++) {
            const uint2 Bw1 = sW1f[(2 * ks + ntl) * 32 + lane];
            mma_f16(l1[0][ntl], xa[0][0], xa[0][1], 0u, 0u, Bw1.x, Bw1.y);
            mma_f16(l1[1][ntl], xa[1][0], xa[1][1], 0u, 0u, Bw1.x, Bw1.y);
        }

        // repack D-frag -> A-frag (relu)
        uint32_t A2[2][4];
        #pragma unroll
        for (int mt = 0; mt < 2; mt++) {
            A2[mt][0] = packh2(fmaxf(l1[mt][0][0], 0.f), fmaxf(l1[mt][0][1], 0.f));
            A2[mt][1] = packh2(fmaxf(l1[mt][0][2], 0.f), fmaxf(l1[mt][0][3], 0.f));
            A2[mt][2] = packh2(fmaxf(l1[mt][1][0], 0.f), fmaxf(l1[mt][1][1], 0.f));
            A2[mt][3] = packh2(fmaxf(l1[mt][1][2], 0.f), fmaxf(l1[mt][1][3], 0.f));
        }

        // L2
        #pragma unroll
        for (int nt = 0; nt < 8; nt++) {
            const uint2 B = sW2f[(ks * 8 + nt) * 32 + lane];
            mma_f16(acc[0][nt], A2[0][0], A2[0][1], A2[0][2], A2[0][3], B.x, B.y);
            mma_f16(acc[1][nt], A2[1][0], A2[1][1], A2[1][2], A2[1][3], B.x, B.y);
        }
    }

    // --- L3 as MMA: relu(acc) @ w3 (N=8 padded; cols 0,1 real) ---
    float o[2][4];
    #pragma unroll
    for (int mt = 0; mt < 2; mt++)
        #pragma unroll
        for (int q = 0; q < 4; q++) o[mt][q] = 0.f;

    #pragma unroll
    for (int ks = 0; ks < 4; ks++) {
        const uint2 Bw3 = sW3f[ks * 32 + lane];
        #pragma unroll
        for (int mt = 0; mt < 2; mt++) {
            const uint32_t a0 = packh2(fmaxf(acc[mt][2 * ks][0], 0.f),
                                       fmaxf(acc[mt][2 * ks][1], 0.f));
            const uint32_t a1 = packh2(fmaxf(acc[mt][2 * ks][2], 0.f),
                                       fmaxf(acc[mt][2 * ks][3], 0.f));
            const uint32_t a2 = packh2(fmaxf(acc[mt][2 * ks + 1][0], 0.f),
                                       fmaxf(acc[mt][2 * ks + 1][1], 0.f));
            const uint32_t a3 = packh2(fmaxf(acc[mt][2 * ks + 1][2], 0.f),
                                       fmaxf(acc[mt][2 * ks + 1][3], 0.f));
            mma_f16(o[mt], a0, a1, a2, a3, Bw3.x, Bw3.y);
        }
    }

    if (kb == 0) {   // these lanes hold output cols 0,1
        const float b30 = sB3[0], b31 = sB3[1];
        #pragma unroll
        for (int mt = 0; mt < 2; mt++) {
            const int r0 = rbase + mt * 16;
            if (r0 < mvalid)
                ((float2*)out)[sIdx[r0]] = make_float2(o[mt][0] + b30,
                                                       o[mt][1] + b31);
            const int r1 = r0 + 8;
            if (r1 < mvalid)
                ((float2*)out)[sIdx[r1]] = make_float2(o[mt][2] + b30,
                                                       o[mt][3] + b31);
        }
    }
}

extern "C" void kernel_launch(void* const* d_in, const int* in_sizes, int n_in,
                              void* d_out, int out_size)
{
    const float* x  = (const float*)d_in[0];
    const float* rW = (const float*)d_in[1];
    const float* rb = (const float*)d_in[2];
    const float* w1 = (const float*)d_in[3];
    const float* b1 = (const float*)d_in[4];
    const float* w2 = (const float*)d_in[5];
    const float* b2 = (const float*)d_in[6];
    const float* w3 = (const float*)d_in[7];
    const float* b3 = (const float*)d_in[8];
    float* out = (float*)d_out;

    const int n_tok = in_sizes[0] / 2;

    void* cnt_addr = nullptr;
    cudaGetSymbolAddress(&cnt_addr, d_cnt);
    cudaMemsetAsync(cnt_addr, 0, 4 * sizeof(int));

    router_kernel<<<n_tok / 512, 256>>>(x, rW, rb, w1, b1, w2, w3, out, n_tok);

    const int max_tiles = n_tok / TILE + 3;   // per-expert ceil slack
    expert_kernel<<<max_tiles, 256>>>(x, b2, b3, out);
}